// round 4
// baseline (speedup 1.0000x reference)
#include <cuda_runtime.h>
#include <math.h>

#define BB 32
#define NN 1000
#define BN (BB*NN)
#define DD 64
#define HID 256
#define OBS 147
#define KSEL 500
#define NEGV (-1e8f)

// ---------------- scratch (device globals; no allocation) ----------------
__device__ float g_x[(size_t)BN*15];
__device__ float g_h[(size_t)BN*DD];
__device__ float g_hs[BN];
__device__ float g_hd[BN];
__device__ float g_comp[(size_t)BN*DD];
__device__ float g_coop[(size_t)BN*DD];
__device__ float g_xp[(size_t)BN*HID];
__device__ float g_scores[2*BN];                  // [0..BN)=f, [BN..2BN)=d
__device__ float g_w[2*BN];                       // pooling weights
__device__ float g_pp[2*BB*4*2*HID];              // pooling partials
__device__ int   g_flag4;                         // 1 if bools are int32, 0 if 1-byte

// ---------------- f32x2 helpers ----------------
__device__ __forceinline__ unsigned long long pk2(float a, float b) {
    unsigned long long r;
    asm("mov.b64 %0, {%1,%2};" : "=l"(r) : "f"(a), "f"(b));
    return r;
}
__device__ __forceinline__ void upk2(unsigned long long v, float& a, float& b) {
    asm("mov.b64 {%0,%1}, %2;" : "=f"(a), "=f"(b) : "l"(v));
}
__device__ __forceinline__ unsigned long long ffma2(unsigned long long a, unsigned long long b,
                                                    unsigned long long c) {
    unsigned long long d;
    asm("fma.rn.f32x2 %0, %1, %2, %3;" : "=l"(d) : "l"(a), "l"(b), "l"(c));
    return d;
}

// ---------------- bool-width detection ----------------
__global__ void detect_kernel(const unsigned char* p, int nbytes) {
    __shared__ int any;
    if (threadIdx.x == 0) any = 0;
    __syncthreads();
    int loc = 0;
    for (int i = threadIdx.x; i < nbytes; i += blockDim.x)
        if ((i & 3) && p[i]) loc = 1;
    if (loc) any = 1;
    __syncthreads();
    if (threadIdx.x == 0) g_flag4 = any ? 0 : 1;
}

__device__ __forceinline__ bool bget(const void* p, size_t idx, int f4) {
    return f4 ? (((const int*)p)[idx] != 0) : (((const unsigned char*)p)[idx] != 0);
}

// ---------------- x = [cs(4), tp(2), vf(9)] ----------------
__global__ void buildx_kernel(const int* __restrict__ op_idx, const float* __restrict__ vf,
                              const float* __restrict__ cs_tab, const float* __restrict__ tp_tab) {
    int idx = blockIdx.x * blockDim.x + threadIdx.x;
    if (idx >= BN) return;
    int n = idx % NN;
    float* xr = g_x + (size_t)idx * 15;
    int op = op_idx[idx];
#pragma unroll
    for (int c = 0; c < 4; c++) xr[c] = cs_tab[n * 4 + c];
    xr[4] = tp_tab[op * 2 + 0];
    xr[5] = tp_tab[op * 2 + 1];
#pragma unroll
    for (int c = 0; c < 9; c++) xr[6 + c] = vf[(size_t)idx * 9 + c];
}

// ---------------- h = x @ W, hd = h.adst, hs = h.asrc ----------------
__global__ __launch_bounds__(256) void h_kernel(const float* __restrict__ xa, int Fa,
                                                const float* __restrict__ xb, int Fb,
                                                const float* __restrict__ W,
                                                const float* __restrict__ asrc,
                                                const float* __restrict__ adst) {
    __shared__ float xs[4][80];
    __shared__ float red[4][2][2];
    int nl = threadIdx.x >> 6, d = threadIdx.x & 63;
    size_t gn = (size_t)blockIdx.x * 4 + nl;
    for (int f = d; f < Fa; f += 64) xs[nl][f] = xa[gn * Fa + f];
    for (int f = d; f < Fb; f += 64) xs[nl][Fa + f] = xb[gn * Fb + f];
    __syncthreads();
    int F = Fa + Fb;
    float acc = 0.f;
    for (int f = 0; f < F; f++) acc = fmaf(xs[nl][f], W[f * DD + d], acc);
    g_h[gn * DD + d] = acc;
    float p1 = acc * adst[d], p2 = acc * asrc[d];
    for (int o = 16; o; o >>= 1) {
        p1 += __shfl_xor_sync(0xffffffffu, p1, o);
        p2 += __shfl_xor_sync(0xffffffffu, p2, o);
    }
    if ((d & 31) == 0) { red[nl][d >> 5][0] = p1; red[nl][d >> 5][1] = p2; }
    __syncthreads();
    if (threadIdx.x < 4) {
        size_t g2 = (size_t)blockIdx.x * 4 + threadIdx.x;
        g_hd[g2] = red[threadIdx.x][0][0] + red[threadIdx.x][1][0];
        g_hs[g2] = red[threadIdx.x][0][1] + red[threadIdx.x][1][1];
    }
}

// ---------------- fused GAT (no max-shift; f32x2 MMA) ----------------
// Block: 64 dst nodes, one batch. 8 warps; each warp 8 dst, lane owns dims (lane, lane+32).
// Tile over j in chunks of 64. Coop phase: p = adj ? exp(leaky(hd+hs+wd*dist)) : 0
// packed as j-pair f32x2 into p_pair[i][jp]; h packed as h_pair[jp][d].
// MMA: acc[g][slot] (f32x2 over j-parity) += p_pair * h_pair.
__global__ __launch_bounds__(256) void gat_kernel(const float* __restrict__ wdp,
                                                  const void* __restrict__ adj,
                                                  const float* __restrict__ dist,
                                                  float* __restrict__ outrep) {
    const float wd = *wdp;
    const int f4 = g_flag4;
    const int b = blockIdx.y;
    const int i0 = blockIdx.x * 64;
    const int t = threadIdx.x;
    const int w = t >> 5, lane = t & 31;

    __shared__ unsigned long long p_pair[64][34];   // [i_loc][jp], pad 34 (16B-aligned rows)
    __shared__ unsigned long long h_pair[32][64];   // [jp][d]
    __shared__ float s_part[4][64];
    __shared__ float s_fin[64];

    // coop-phase identity
    const int i_loc = t & 63;
    const int qq = t >> 6;               // 0..3, owns j = qq*16 .. qq*16+15
    const int iG = i0 + i_loc;
    const bool ivalid = iG < NN;
    const float hdv = ivalid ? g_hd[b * NN + iG] : 0.f;
    float sacc = 0.f;

    // h-fill identity
    const int d2 = t & 31;
    const int jh = t >> 5;               // 0..7, owns j = jh*8 .. jh*8+7

    const size_t abase = (size_t)b * NN * NN;
    const float* hb = g_h + (size_t)b * NN * DD;
    const float* hsb = g_hs + b * NN;

    // MMA accumulators: 8 dst x 2 dim-slots, f32x2 split over j-parity
    unsigned long long acc[8][2];
#pragma unroll
    for (int g = 0; g < 8; g++) { acc[g][0] = 0ull; acc[g][1] = 0ull; }
    const int iw = w * 8;

    for (int j0 = 0; j0 < NN; j0 += 64) {
        __syncthreads();
        // ---- fill h_pair ----
#pragma unroll
        for (int jj = 0; jj < 8; jj++) {
            int j = jh * 8 + jj;
            int jG = j0 + j;
            float h0 = 0.f, h1 = 0.f;
            if (jG < NN) {
                h0 = hb[(size_t)jG * DD + d2];
                h1 = hb[(size_t)jG * DD + d2 + 32];
            }
            float* hp = (float*)&h_pair[j >> 1][0];
            hp[d2 * 2 + (j & 1)] = h0;
            hp[(d2 + 32) * 2 + (j & 1)] = h1;
        }
        // ---- fill p_pair ----
        float pprev = 0.f;
#pragma unroll
        for (int k = 0; k < 16; k++) {
            int j = qq * 16 + k;
            int jG = j0 + j;
            float p = 0.f;
            if (ivalid && jG < NN) {
                if (bget(adj, abase + (size_t)jG * NN + iG, f4)) {
                    float ev = hdv + hsb[jG] + wd * __ldg(&dist[(size_t)jG * NN + iG]);
                    ev = (ev >= 0.f) ? ev : 0.2f * ev;
                    p = __expf(ev);
                }
            }
            sacc += p;
            if (k & 1) p_pair[i_loc][qq * 8 + (k >> 1)] = pk2(pprev, p);
            else pprev = p;
        }
        __syncthreads();
        // ---- MMA phase ----
#pragma unroll 4
        for (int q = 0; q < 16; q++) {
            unsigned long long h0a = h_pair[2 * q][lane];
            unsigned long long h0b = h_pair[2 * q][lane + 32];
            unsigned long long h1a = h_pair[2 * q + 1][lane];
            unsigned long long h1b = h_pair[2 * q + 1][lane + 32];
#pragma unroll
            for (int g = 0; g < 8; g++) {
                ulonglong2 pq = *(const ulonglong2*)&p_pair[iw + g][2 * q];
                acc[g][0] = ffma2(pq.x, h0a, acc[g][0]);
                acc[g][1] = ffma2(pq.x, h0b, acc[g][1]);
                acc[g][0] = ffma2(pq.y, h1a, acc[g][0]);
                acc[g][1] = ffma2(pq.y, h1b, acc[g][1]);
            }
        }
    }
    // ---- reduce s per dst ----
    s_part[qq][i_loc] = sacc;
    __syncthreads();
    if (t < 64) s_fin[t] = s_part[0][t] + s_part[1][t] + s_part[2][t] + s_part[3][t];
    __syncthreads();
    // ---- finalize: divide, elu, store ----
#pragma unroll
    for (int g = 0; g < 8; g++) {
        int il = iw + g;
        int ig = i0 + il;
        if (ig >= NN) continue;
        float s = s_fin[il];
        float inv = (s > 0.f) ? 1.f / s : 0.f;
        float a0, a1, b0, b1;
        upk2(acc[g][0], a0, a1);
        upk2(acc[g][1], b0, b1);
        float vx = (a0 + a1) * inv;
        float vy = (b0 + b1) * inv;
        vx = (vx > 0.f) ? vx : expm1f(vx);
        vy = (vy > 0.f) ? vy : expm1f(vy);
        float* orow = outrep + ((size_t)b * NN + ig) * DD;
        orow[lane] = vx;
        orow[lane + 32] = vy;
    }
}

// ---------------- x_p = sag @ Wp + bp, fused scores ----------------
__global__ __launch_bounds__(256) void xp_kernel(const int* __restrict__ time_idx,
                                                 const int* __restrict__ op_idx,
                                                 const float* __restrict__ vf,
                                                 const float* __restrict__ time_tab,
                                                 const float* __restrict__ cs_tab,
                                                 const float* __restrict__ tp_tab,
                                                 const float* __restrict__ Wp,
                                                 const float* __restrict__ bp,
                                                 const float* __restrict__ vpd,
                                                 const float* __restrict__ vpf,
                                                 float* __restrict__ xp) {
    __shared__ float sag[OBS][8];
    __shared__ float sred[8][16];
    int w = threadIdx.x >> 5, lane = threadIdx.x & 31;
    size_t gn0 = (size_t)blockIdx.x * 8;
    {
        size_t gn = gn0 + w;
        int n = (int)(gn % NN);
        int ti = time_idx[gn], op = op_idx[gn];
        for (int f = lane; f < OBS; f += 32) {
            float v;
            if (f < 4)       v = time_tab[ti * 4 + f];
            else if (f < 8)  v = cs_tab[n * 4 + (f - 4)];
            else if (f < 10) v = tp_tab[op * 2 + (f - 8)];
            else if (f < 19) v = vf[gn * 9 + (f - 10)];
            else if (f < 83) v = g_comp[gn * 64 + (f - 19)];
            else             v = g_coop[gn * 64 + (f - 83)];
            sag[f][w] = v;
        }
    }
    __syncthreads();
    int h = threadIdx.x;
    float bv = bp[h];
    unsigned long long acc2[4];
    unsigned long long bv2 = pk2(bv, bv);
#pragma unroll
    for (int k = 0; k < 4; k++) acc2[k] = bv2;
#pragma unroll 3
    for (int f = 0; f < OBS; f++) {
        float wv = Wp[f * HID + h];
        unsigned long long wv2 = pk2(wv, wv);
        ulonglong2 sA = *(const ulonglong2*)&sag[f][0];
        ulonglong2 sB = *(const ulonglong2*)&sag[f][4];
        acc2[0] = ffma2(wv2, sA.x, acc2[0]);
        acc2[1] = ffma2(wv2, sA.y, acc2[1]);
        acc2[2] = ffma2(wv2, sB.x, acc2[2]);
        acc2[3] = ffma2(wv2, sB.y, acc2[3]);
    }
    float xv[8];
#pragma unroll
    for (int k = 0; k < 4; k++) upk2(acc2[k], xv[2 * k], xv[2 * k + 1]);
#pragma unroll
    for (int nl = 0; nl < 8; nl++) xp[(gn0 + nl) * HID + h] = xv[nl];
    // fused scores: per node, reduce xv*vpf and xv*vpd over h
    float vdv = vpd[h], vfv = vpf[h];
#pragma unroll
    for (int nl = 0; nl < 8; nl++) {
        float sf = xv[nl] * vfv;
        float sd = xv[nl] * vdv;
        for (int o = 16; o; o >>= 1) {
            sf += __shfl_xor_sync(0xffffffffu, sf, o);
            sd += __shfl_xor_sync(0xffffffffu, sd, o);
        }
        if (lane == 0) { sred[w][2 * nl] = sf; sred[w][2 * nl + 1] = sd; }
    }
    __syncthreads();
    if (threadIdx.x < 16) {
        float s = 0.f;
#pragma unroll
        for (int w2 = 0; w2 < 8; w2++) s += sred[w2][threadIdx.x];
        int nl = threadIdx.x >> 1;
        size_t gn = gn0 + nl;
        if (threadIdx.x & 1) g_scores[BN + gn] = s;   // d
        else                 g_scores[gn] = s;        // f
    }
}

// ---------------- pooling: weights (sort + softmax) ----------------
__global__ __launch_bounds__(256) void pool_w_kernel(const void* __restrict__ dpcs) {
    int b = blockIdx.x, type = blockIdx.y;  // 0 = f (~mark), 1 = d (mark)
    __shared__ float sc[1024];
    __shared__ float sraw[NN];
    __shared__ float red[256];
    int f4 = g_flag4;
    const float* srow = g_scores + (size_t)type * BN + (size_t)b * NN;

    float lm = -INFINITY;
    for (int n = threadIdx.x; n < NN; n += 256) lm = fmaxf(lm, srow[n]);
    red[threadIdx.x] = lm;
    __syncthreads();
    for (int o = 128; o; o >>= 1) {
        if (threadIdx.x < o) red[threadIdx.x] = fmaxf(red[threadIdx.x], red[threadIdx.x + o]);
        __syncthreads();
    }
    float gm = red[0];
    __syncthreads();

    for (int n = threadIdx.x; n < 1024; n += 256) {
        float v = -INFINITY;
        if (n < NN) {
            bool mk = bget(dpcs, (size_t)b * NN + n, f4);
            bool valid = type ? mk : !mk;
            float sv = valid ? (srow[n] - gm) : NEGV;
            sraw[n] = sv;
            v = sv;
        }
        sc[n] = v;
    }
    __syncthreads();

    for (int k = 2; k <= 1024; k <<= 1)
        for (int j = k >> 1; j > 0; j >>= 1) {
            for (int i = threadIdx.x; i < 1024; i += 256) {
                int ixj = i ^ j;
                if (ixj > i) {
                    float a = sc[i], c = sc[ixj];
                    bool dirAsc = (i & k) == 0;
                    bool sw = dirAsc ? (a < c) : (a > c);
                    if (sw) { sc[i] = c; sc[ixj] = a; }
                }
            }
            __syncthreads();
        }
    float th = sc[KSEL - 1];
    float mx = sc[0];

    float part = 0.f;
    for (int n = threadIdx.x; n < NN; n += 256) {
        float sv = sraw[n];
        float p = (sv >= th) ? __expf(sv - mx) : 0.f;
        sraw[n] = p;
        part += p;
    }
    __syncthreads();
    red[threadIdx.x] = part;
    __syncthreads();
    for (int o = 128; o; o >>= 1) {
        if (threadIdx.x < o) red[threadIdx.x] += red[threadIdx.x + o];
        __syncthreads();
    }
    float invS = 1.f / red[0];
    float* wrow = g_w + (size_t)type * BN + (size_t)b * NN;
    for (int n = threadIdx.x; n < NN; n += 256) wrow[n] = sraw[n] * invS;
}

// ---------------- pooling: partial weighted sum/max over n-chunks ----------------
__global__ __launch_bounds__(256) void pool_sum_kernel(const float* __restrict__ xp) {
    int b = blockIdx.x, type = blockIdx.y, q = blockIdx.z;
    int h = threadIdx.x;
    const float* wrow = g_w + (size_t)type * BN + (size_t)b * NN;
    const float* xpb = xp + (size_t)b * NN * HID + h;
    int n0 = q * 250, n1 = n0 + 250;
    float sum = 0.f, mxv = -INFINITY;
    for (int n = n0; n < n1; n++) {
        float xv = wrow[n] * xpb[(size_t)n * HID];
        sum += xv;
        mxv = fmaxf(mxv, xv);
    }
    float* pp = g_pp + ((((size_t)type * BB + b) * 4 + q) * 2) * HID;
    pp[h] = sum;
    pp[HID + h] = mxv;
}

// ---------------- pooling: combine partials ----------------
__global__ void pool_fin_kernel(float* __restrict__ out) {
    int b = blockIdx.x, type = blockIdx.y;
    int h = threadIdx.x;
    float sum = 0.f, mxv = -INFINITY;
#pragma unroll
    for (int q = 0; q < 4; q++) {
        const float* pp = g_pp + ((((size_t)type * BB + b) * 4 + q) * 2) * HID;
        sum += pp[h];
        mxv = fmaxf(mxv, pp[HID + h]);
    }
    float* ob = out + (size_t)b * 1024 + type * 512;
    ob[h] = sum;
    ob[256 + h] = mxv;
}

// ---------------- launch ----------------
extern "C" void kernel_launch(void* const* d_in, const int* in_sizes, int n_in,
                              void* d_out, int out_size) {
    const int*   time_idx = (const int*)d_in[0];
    const int*   op_idx   = (const int*)d_in[1];
    const float* vf       = (const float*)d_in[2];
    const void*  dpcs     = d_in[3];
    const void*  adjc     = d_in[4];
    const void*  adjo     = d_in[5];
    const float* dist     = (const float*)d_in[6];
    const float* time_tab = (const float*)d_in[7];
    const float* tp_tab   = (const float*)d_in[8];
    const float* cs_tab   = (const float*)d_in[9];
    const float* Wc       = (const float*)d_in[10];
    const float* asrc_c   = (const float*)d_in[11];
    const float* adst_c   = (const float*)d_in[12];
    const float* wd_c     = (const float*)d_in[13];
    const float* Wco      = (const float*)d_in[14];
    const float* asrc_co  = (const float*)d_in[15];
    const float* adst_co  = (const float*)d_in[16];
    const float* wd_co    = (const float*)d_in[17];
    const float* Wp       = (const float*)d_in[18];
    const float* bp       = (const float*)d_in[19];
    const float* vpd      = (const float*)d_in[20];
    const float* vpf      = (const float*)d_in[21];
    float* out = (float*)d_out;

    float *px, *pcomp, *pcoop, *pxp;
    cudaGetSymbolAddress((void**)&px,    g_x);
    cudaGetSymbolAddress((void**)&pcomp, g_comp);
    cudaGetSymbolAddress((void**)&pcoop, g_coop);
    cudaGetSymbolAddress((void**)&pxp,   g_xp);

    detect_kernel<<<1, 256>>>((const unsigned char*)adjc, 32000);
    buildx_kernel<<<BN / 256 + 1, 256>>>(op_idx, vf, cs_tab, tp_tab);

    h_kernel<<<BN / 4, 256>>>(px, 15, (const float*)nullptr, 0, Wc, asrc_c, adst_c);
    gat_kernel<<<dim3(16, BB), 256>>>(wd_c, adjc, dist, pcomp);

    h_kernel<<<BN / 4, 256>>>(px, 15, pcomp, 64, Wco, asrc_co, adst_co);
    gat_kernel<<<dim3(16, BB), 256>>>(wd_co, adjo, dist, pcoop);

    xp_kernel<<<BN / 8, 256>>>(time_idx, op_idx, vf, time_tab, cs_tab, tp_tab,
                               Wp, bp, vpd, vpf, pxp);
    pool_w_kernel<<<dim3(BB, 2), 256>>>(dpcs);
    pool_sum_kernel<<<dim3(BB, 2, 4), 256>>>(pxp);
    pool_fin_kernel<<<dim3(BB, 2), 256>>>(out);
}

// round 5
// speedup vs baseline: 1.8423x; 1.8423x over previous
#include <cuda_runtime.h>
#include <math.h>

#define BB 32
#define NN 1000
#define BN (BB*NN)
#define DD 64
#define HID 256
#define OBS 147
#define KSEL 500
#define NEGV (-1e8f)
#define NIT 16          // i-tiles of 64
#define NJC 4           // j-chunks of 256

// ---------------- scratch (device globals; no allocation) ----------------
__device__ float g_x[(size_t)BN*15];
__device__ float g_hpair[(size_t)BB*512*128];     // [b][jp][d*2+(j&1)], zero-padded jp>=500
__device__ float g_hs[BN];
__device__ float g_hd[BN];
__device__ float g_comp[(size_t)BN*DD];
__device__ float g_coop[(size_t)BN*DD];
__device__ float g_pacc[(size_t)BB*NIT*NJC*4096]; // partial acc per block
__device__ float g_spart[(size_t)BB*NIT*NJC*64];  // partial s per block
__device__ float g_xp[(size_t)BN*HID];
__device__ float g_scores[2*BN];
__device__ float g_w[2*BN];
__device__ float g_pp[2*BB*4*2*HID];
__device__ int   g_flag4;

// ---------------- f32x2 helpers ----------------
__device__ __forceinline__ unsigned long long pk2(float a, float b) {
    unsigned long long r;
    asm("mov.b64 %0, {%1,%2};" : "=l"(r) : "f"(a), "f"(b));
    return r;
}
__device__ __forceinline__ void upk2(unsigned long long v, float& a, float& b) {
    asm("mov.b64 {%0,%1}, %2;" : "=f"(a), "=f"(b) : "l"(v));
}
__device__ __forceinline__ unsigned long long ffma2(unsigned long long a, unsigned long long b,
                                                    unsigned long long c) {
    unsigned long long d;
    asm("fma.rn.f32x2 %0, %1, %2, %3;" : "=l"(d) : "l"(a), "l"(b), "l"(c));
    return d;
}

// ---------------- bool-width detection ----------------
__global__ void detect_kernel(const unsigned char* p, int nbytes) {
    __shared__ int any;
    if (threadIdx.x == 0) any = 0;
    __syncthreads();
    int loc = 0;
    for (int i = threadIdx.x; i < nbytes; i += blockDim.x)
        if ((i & 3) && p[i]) loc = 1;
    if (loc) any = 1;
    __syncthreads();
    if (threadIdx.x == 0) g_flag4 = any ? 0 : 1;
}

__device__ __forceinline__ bool bget(const void* p, size_t idx, int f4) {
    return f4 ? (((const int*)p)[idx] != 0) : (((const unsigned char*)p)[idx] != 0);
}

// ---------------- x = [cs(4), tp(2), vf(9)] ----------------
__global__ void buildx_kernel(const int* __restrict__ op_idx, const float* __restrict__ vf,
                              const float* __restrict__ cs_tab, const float* __restrict__ tp_tab) {
    int idx = blockIdx.x * blockDim.x + threadIdx.x;
    if (idx >= BN) return;
    int n = idx % NN;
    float* xr = g_x + (size_t)idx * 15;
    int op = op_idx[idx];
#pragma unroll
    for (int c = 0; c < 4; c++) xr[c] = cs_tab[n * 4 + c];
    xr[4] = tp_tab[op * 2 + 0];
    xr[5] = tp_tab[op * 2 + 1];
#pragma unroll
    for (int c = 0; c < 9; c++) xr[6 + c] = vf[(size_t)idx * 9 + c];
}

// ---------------- h = x @ W (pair-packed out), hd, hs ----------------
__global__ __launch_bounds__(256) void h_kernel(const float* __restrict__ xa, int Fa,
                                                const float* __restrict__ xb, int Fb,
                                                const float* __restrict__ W,
                                                const float* __restrict__ asrc,
                                                const float* __restrict__ adst) {
    __shared__ float xs[4][80];
    __shared__ float red[4][2][2];
    int nl = threadIdx.x >> 6, d = threadIdx.x & 63;
    size_t gn = (size_t)blockIdx.x * 4 + nl;
    for (int f = d; f < Fa; f += 64) xs[nl][f] = xa[gn * Fa + f];
    for (int f = d; f < Fb; f += 64) xs[nl][Fa + f] = xb[gn * Fb + f];
    __syncthreads();
    int F = Fa + Fb;
    float acc = 0.f;
    for (int f = 0; f < F; f++) acc = fmaf(xs[nl][f], W[f * DD + d], acc);
    int b = (int)(gn / NN), j = (int)(gn - (size_t)b * NN);
    g_hpair[((size_t)b * 512 + (j >> 1)) * 128 + d * 2 + (j & 1)] = acc;
    float p1 = acc * adst[d], p2 = acc * asrc[d];
    for (int o = 16; o; o >>= 1) {
        p1 += __shfl_xor_sync(0xffffffffu, p1, o);
        p2 += __shfl_xor_sync(0xffffffffu, p2, o);
    }
    if ((d & 31) == 0) { red[nl][d >> 5][0] = p1; red[nl][d >> 5][1] = p2; }
    __syncthreads();
    if (threadIdx.x < 4) {
        size_t g2 = (size_t)blockIdx.x * 4 + threadIdx.x;
        g_hd[g2] = red[threadIdx.x][0][0] + red[threadIdx.x][1][0];
        g_hs[g2] = red[threadIdx.x][0][1] + red[threadIdx.x][1][1];
    }
}

// ---------------- fused GAT partial: (b, i-tile 64, j-chunk 256) ----------------
__global__ __launch_bounds__(256, 3) void gat_kernel(const float* __restrict__ wdp,
                                                     const void* __restrict__ adj,
                                                     const float* __restrict__ dist) {
    const float wd = *wdp;
    const int f4 = g_flag4;
    const int it = blockIdx.x, jc = blockIdx.y, b = blockIdx.z;
    const int i0 = it * 64;
    const int jbase = jc * 256;
    const int t = threadIdx.x;
    const int w = t >> 5, lane = t & 31;
    const int pidx = (b * NJC + jc) * NIT + it;

    __shared__ unsigned long long p_pair[64][33];   // pad 33: conflict-free 8B stores
    __shared__ unsigned long long h_pair[32][64];   // [jp][d]
    __shared__ float hs_s[256];
    __shared__ float s_part[4][64];

    const int i_loc = t & 63;
    const int qq = t >> 6;
    const int iG = i0 + i_loc;
    const bool ivalid = iG < NN;
    const float hdv = ivalid ? g_hd[b * NN + iG] : 0.f;
    float sacc = 0.f;

    // stage hs for the chunk
    {
        int jG = jbase + t;
        hs_s[t] = (t < 256 && jG < NN) ? g_hs[b * NN + jG] : 0.f;
    }

    const unsigned char* ab = (const unsigned char*)adj;
    const int mult = f4 ? 4 : 1;
    const size_t abyte = (size_t)b * NN * NN * mult;

    unsigned long long acc[8][2];
#pragma unroll
    for (int g = 0; g < 8; g++) { acc[g][0] = 0ull; acc[g][1] = 0ull; }
    const int iw = w * 8;

    unsigned char av[16];
    float dv[16];
    // prefetch subtile 0
#pragma unroll
    for (int k = 0; k < 16; k++) {
        int jG = jbase + qq * 16 + k;
        bool ok = ivalid && (jG < NN);
        av[k] = ok ? ab[((size_t)jG * NN + iG) * mult + abyte] : 0;
        dv[k] = ok ? __ldg(&dist[(size_t)jG * NN + iG]) : 0.f;
    }
    __syncthreads();

    const float4* hg4base = ((const float4*)g_hpair) + (size_t)b * 16384 + (size_t)jc * 128 * 32;

    for (int st = 0; st < 4; st++) {
        // ---- fill h_pair: flat coalesced copy (pair-packed in global) ----
        {
            const float4* hg4 = hg4base + (size_t)st * 32 * 32;
            float4* hp4 = (float4*)&h_pair[0][0];
            hp4[t] = hg4[t];
            hp4[t + 256] = hg4[t + 256];
            hp4[t + 512] = hg4[t + 512];
            hp4[t + 768] = hg4[t + 768];
        }
        // ---- compute p from prefetched regs ----
        {
            int jl0 = st * 64 + qq * 16;
            float pprev = 0.f;
#pragma unroll
            for (int k = 0; k < 16; k++) {
                float p = 0.f;
                if (av[k]) {
                    float ev = hdv + hs_s[jl0 + k] + wd * dv[k];
                    ev = (ev >= 0.f) ? ev : 0.2f * ev;
                    p = __expf(ev);
                }
                sacc += p;
                if (k & 1) p_pair[i_loc][qq * 8 + (k >> 1)] = pk2(pprev, p);
                else pprev = p;
            }
        }
        // ---- prefetch next subtile (overlaps MMA) ----
        if (st < 3) {
            int jb2 = jbase + (st + 1) * 64;
#pragma unroll
            for (int k = 0; k < 16; k++) {
                int jG = jb2 + qq * 16 + k;
                bool ok = ivalid && (jG < NN);
                av[k] = ok ? ab[((size_t)jG * NN + iG) * mult + abyte] : 0;
                dv[k] = ok ? __ldg(&dist[(size_t)jG * NN + iG]) : 0.f;
            }
        }
        __syncthreads();
        // ---- MMA ----
#pragma unroll 4
        for (int q = 0; q < 16; q++) {
            unsigned long long h0a = h_pair[2 * q][lane];
            unsigned long long h0b = h_pair[2 * q][lane + 32];
            unsigned long long h1a = h_pair[2 * q + 1][lane];
            unsigned long long h1b = h_pair[2 * q + 1][lane + 32];
#pragma unroll
            for (int g = 0; g < 8; g++) {
                unsigned long long pa = p_pair[iw + g][2 * q];
                unsigned long long pb = p_pair[iw + g][2 * q + 1];
                acc[g][0] = ffma2(pa, h0a, acc[g][0]);
                acc[g][1] = ffma2(pa, h0b, acc[g][1]);
                acc[g][0] = ffma2(pb, h1a, acc[g][0]);
                acc[g][1] = ffma2(pb, h1b, acc[g][1]);
            }
        }
        __syncthreads();
    }
    // ---- store partial s ----
    s_part[qq][i_loc] = sacc;
    __syncthreads();
    if (t < 64)
        g_spart[(size_t)pidx * 64 + t] = s_part[0][t] + s_part[1][t] + s_part[2][t] + s_part[3][t];
    // ---- store partial acc ----
    float* pw = g_pacc + (size_t)pidx * 4096;
#pragma unroll
    for (int g = 0; g < 8; g++) {
        float a0, a1, b0, b1;
        upk2(acc[g][0], a0, a1);
        upk2(acc[g][1], b0, b1);
        int il = iw + g;
        pw[il * 64 + lane] = a0 + a1;
        pw[il * 64 + lane + 32] = b0 + b1;
    }
}

// ---------------- GAT finalize: reduce chunks, divide, elu ----------------
__global__ __launch_bounds__(256) void gat_fin_kernel(float* __restrict__ outrep) {
    int it = blockIdx.x, b = blockIdx.y;
    int t = threadIdx.x;
    __shared__ float s_tot[64];
    if (t < 64) {
        float s = 0.f;
#pragma unroll
        for (int jcc = 0; jcc < NJC; jcc++)
            s += g_spart[(size_t)((b * NJC + jcc) * NIT + it) * 64 + t];
        s_tot[t] = s;
    }
    __syncthreads();
#pragma unroll
    for (int e = 0; e < 16; e++) {
        int idx = t + e * 256;
        int il = idx >> 6, d = idx & 63;
        int ig = it * 64 + il;
        if (ig >= NN) continue;
        float a = 0.f;
#pragma unroll
        for (int jcc = 0; jcc < NJC; jcc++)
            a += g_pacc[(size_t)((b * NJC + jcc) * NIT + it) * 4096 + idx];
        float s = s_tot[il];
        float inv = (s > 0.f) ? 1.f / s : 0.f;
        float v = a * inv;
        v = (v > 0.f) ? v : expm1f(v);
        outrep[((size_t)b * NN + ig) * DD + d] = v;
    }
}

// ---------------- x_p = sag @ Wp + bp, fused scores ----------------
__global__ __launch_bounds__(256) void xp_kernel(const int* __restrict__ time_idx,
                                                 const int* __restrict__ op_idx,
                                                 const float* __restrict__ vf,
                                                 const float* __restrict__ time_tab,
                                                 const float* __restrict__ cs_tab,
                                                 const float* __restrict__ tp_tab,
                                                 const float* __restrict__ Wp,
                                                 const float* __restrict__ bp,
                                                 const float* __restrict__ vpd,
                                                 const float* __restrict__ vpf,
                                                 float* __restrict__ xp) {
    __shared__ float sag[OBS][8];
    __shared__ float sred[8][16];
    int w = threadIdx.x >> 5, lane = threadIdx.x & 31;
    size_t gn0 = (size_t)blockIdx.x * 8;
    {
        size_t gn = gn0 + w;
        int n = (int)(gn % NN);
        int ti = time_idx[gn], op = op_idx[gn];
        for (int f = lane; f < OBS; f += 32) {
            float v;
            if (f < 4)       v = time_tab[ti * 4 + f];
            else if (f < 8)  v = cs_tab[n * 4 + (f - 4)];
            else if (f < 10) v = tp_tab[op * 2 + (f - 8)];
            else if (f < 19) v = vf[gn * 9 + (f - 10)];
            else if (f < 83) v = g_comp[gn * 64 + (f - 19)];
            else             v = g_coop[gn * 64 + (f - 83)];
            sag[f][w] = v;
        }
    }
    __syncthreads();
    int h = threadIdx.x;
    float bv = bp[h];
    unsigned long long acc2[4];
    unsigned long long bv2 = pk2(bv, bv);
#pragma unroll
    for (int k = 0; k < 4; k++) acc2[k] = bv2;
#pragma unroll 3
    for (int f = 0; f < OBS; f++) {
        float wv = Wp[f * HID + h];
        unsigned long long wv2 = pk2(wv, wv);
        ulonglong2 sA = *(const ulonglong2*)&sag[f][0];
        ulonglong2 sB = *(const ulonglong2*)&sag[f][4];
        acc2[0] = ffma2(wv2, sA.x, acc2[0]);
        acc2[1] = ffma2(wv2, sA.y, acc2[1]);
        acc2[2] = ffma2(wv2, sB.x, acc2[2]);
        acc2[3] = ffma2(wv2, sB.y, acc2[3]);
    }
    float xv[8];
#pragma unroll
    for (int k = 0; k < 4; k++) upk2(acc2[k], xv[2 * k], xv[2 * k + 1]);
#pragma unroll
    for (int nl = 0; nl < 8; nl++) xp[(gn0 + nl) * HID + h] = xv[nl];
    float vdv = vpd[h], vfv = vpf[h];
#pragma unroll
    for (int nl = 0; nl < 8; nl++) {
        float sf = xv[nl] * vfv;
        float sd = xv[nl] * vdv;
        for (int o = 16; o; o >>= 1) {
            sf += __shfl_xor_sync(0xffffffffu, sf, o);
            sd += __shfl_xor_sync(0xffffffffu, sd, o);
        }
        if (lane == 0) { sred[w][2 * nl] = sf; sred[w][2 * nl + 1] = sd; }
    }
    __syncthreads();
    if (threadIdx.x < 16) {
        float s = 0.f;
#pragma unroll
        for (int w2 = 0; w2 < 8; w2++) s += sred[w2][threadIdx.x];
        int nl = threadIdx.x >> 1;
        size_t gn = gn0 + nl;
        if (threadIdx.x & 1) g_scores[BN + gn] = s;
        else                 g_scores[gn] = s;
    }
}

// ---------------- pooling: weights (sort + softmax) ----------------
__global__ __launch_bounds__(256) void pool_w_kernel(const void* __restrict__ dpcs) {
    int b = blockIdx.x, type = blockIdx.y;
    __shared__ float sc[1024];
    __shared__ float sraw[NN];
    __shared__ float red[256];
    int f4 = g_flag4;
    const float* srow = g_scores + (size_t)type * BN + (size_t)b * NN;

    float lm = -INFINITY;
    for (int n = threadIdx.x; n < NN; n += 256) lm = fmaxf(lm, srow[n]);
    red[threadIdx.x] = lm;
    __syncthreads();
    for (int o = 128; o; o >>= 1) {
        if (threadIdx.x < o) red[threadIdx.x] = fmaxf(red[threadIdx.x], red[threadIdx.x + o]);
        __syncthreads();
    }
    float gm = red[0];
    __syncthreads();

    for (int n = threadIdx.x; n < 1024; n += 256) {
        float v = -INFINITY;
        if (n < NN) {
            bool mk = bget(dpcs, (size_t)b * NN + n, f4);
            bool valid = type ? mk : !mk;
            float sv = valid ? (srow[n] - gm) : NEGV;
            sraw[n] = sv;
            v = sv;
        }
        sc[n] = v;
    }
    __syncthreads();

    for (int k = 2; k <= 1024; k <<= 1)
        for (int j = k >> 1; j > 0; j >>= 1) {
            for (int i = threadIdx.x; i < 1024; i += 256) {
                int ixj = i ^ j;
                if (ixj > i) {
                    float a = sc[i], c = sc[ixj];
                    bool dirAsc = (i & k) == 0;
                    bool sw = dirAsc ? (a < c) : (a > c);
                    if (sw) { sc[i] = c; sc[ixj] = a; }
                }
            }
            __syncthreads();
        }
    float th = sc[KSEL - 1];
    float mx = sc[0];

    float part = 0.f;
    for (int n = threadIdx.x; n < NN; n += 256) {
        float sv = sraw[n];
        float p = (sv >= th) ? __expf(sv - mx) : 0.f;
        sraw[n] = p;
        part += p;
    }
    __syncthreads();
    red[threadIdx.x] = part;
    __syncthreads();
    for (int o = 128; o; o >>= 1) {
        if (threadIdx.x < o) red[threadIdx.x] += red[threadIdx.x + o];
        __syncthreads();
    }
    float invS = 1.f / red[0];
    float* wrow = g_w + (size_t)type * BN + (size_t)b * NN;
    for (int n = threadIdx.x; n < NN; n += 256) wrow[n] = sraw[n] * invS;
}

// ---------------- pooling: partial weighted sum/max ----------------
__global__ __launch_bounds__(256) void pool_sum_kernel(const float* __restrict__ xp) {
    int b = blockIdx.x, type = blockIdx.y, q = blockIdx.z;
    int h = threadIdx.x;
    const float* wrow = g_w + (size_t)type * BN + (size_t)b * NN;
    const float* xpb = xp + (size_t)b * NN * HID + h;
    int n0 = q * 250, n1 = n0 + 250;
    float sum = 0.f, mxv = -INFINITY;
    for (int n = n0; n < n1; n++) {
        float xv = wrow[n] * xpb[(size_t)n * HID];
        sum += xv;
        mxv = fmaxf(mxv, xv);
    }
    float* pp = g_pp + ((((size_t)type * BB + b) * 4 + q) * 2) * HID;
    pp[h] = sum;
    pp[HID + h] = mxv;
}

// ---------------- pooling: combine ----------------
__global__ void pool_fin_kernel(float* __restrict__ out) {
    int b = blockIdx.x, type = blockIdx.y;
    int h = threadIdx.x;
    float sum = 0.f, mxv = -INFINITY;
#pragma unroll
    for (int q = 0; q < 4; q++) {
        const float* pp = g_pp + ((((size_t)type * BB + b) * 4 + q) * 2) * HID;
        sum += pp[h];
        mxv = fmaxf(mxv, pp[HID + h]);
    }
    float* ob = out + (size_t)b * 1024 + type * 512;
    ob[h] = sum;
    ob[256 + h] = mxv;
}

// ---------------- launch ----------------
extern "C" void kernel_launch(void* const* d_in, const int* in_sizes, int n_in,
                              void* d_out, int out_size) {
    const int*   time_idx = (const int*)d_in[0];
    const int*   op_idx   = (const int*)d_in[1];
    const float* vf       = (const float*)d_in[2];
    const void*  dpcs     = d_in[3];
    const void*  adjc     = d_in[4];
    const void*  adjo     = d_in[5];
    const float* dist     = (const float*)d_in[6];
    const float* time_tab = (const float*)d_in[7];
    const float* tp_tab   = (const float*)d_in[8];
    const float* cs_tab   = (const float*)d_in[9];
    const float* Wc       = (const float*)d_in[10];
    const float* asrc_c   = (const float*)d_in[11];
    const float* adst_c   = (const float*)d_in[12];
    const float* wd_c     = (const float*)d_in[13];
    const float* Wco      = (const float*)d_in[14];
    const float* asrc_co  = (const float*)d_in[15];
    const float* adst_co  = (const float*)d_in[16];
    const float* wd_co    = (const float*)d_in[17];
    const float* Wp       = (const float*)d_in[18];
    const float* bp       = (const float*)d_in[19];
    const float* vpd      = (const float*)d_in[20];
    const float* vpf      = (const float*)d_in[21];
    float* out = (float*)d_out;

    float *px, *pcomp, *pcoop, *pxp;
    cudaGetSymbolAddress((void**)&px,    g_x);
    cudaGetSymbolAddress((void**)&pcomp, g_comp);
    cudaGetSymbolAddress((void**)&pcoop, g_coop);
    cudaGetSymbolAddress((void**)&pxp,   g_xp);

    detect_kernel<<<1, 256>>>((const unsigned char*)adjc, 32000);
    buildx_kernel<<<BN / 256 + 1, 256>>>(op_idx, vf, cs_tab, tp_tab);

    h_kernel<<<BN / 4, 256>>>(px, 15, (const float*)nullptr, 0, Wc, asrc_c, adst_c);
    gat_kernel<<<dim3(NIT, NJC, BB), 256>>>(wd_c, adjc, dist);
    gat_fin_kernel<<<dim3(NIT, BB), 256>>>(pcomp);

    h_kernel<<<BN / 4, 256>>>(px, 15, pcomp, 64, Wco, asrc_co, adst_co);
    gat_kernel<<<dim3(NIT, NJC, BB), 256>>>(wd_co, adjo, dist);
    gat_fin_kernel<<<dim3(NIT, BB), 256>>>(pcoop);

    xp_kernel<<<BN / 8, 256>>>(time_idx, op_idx, vf, time_tab, cs_tab, tp_tab,
                               Wp, bp, vpd, vpf, pxp);
    pool_w_kernel<<<dim3(BB, 2), 256>>>(dpcs);
    pool_sum_kernel<<<dim3(BB, 2, 4), 256>>>(pxp);
    pool_fin_kernel<<<dim3(BB, 2), 256>>>(out);
}